// round 13
// baseline (speedup 1.0000x reference)
#include <cuda_runtime.h>
#include <cuda_bf16.h>

// TextureMartingaleModule: per-channel 3x3 GLCM features, zero padding.
// x: [8,16,256,256] f32 -> out: [8,64,256,256] f32
//   contrast    = mean(((p-mean)/std)^2),  std = sqrt(sd/8)+eps
//   energy      = mean(p^2)
//   entropy     = -mean(p*log(p+eps))
//   homogeneity = 1 / mean(1 + |p-mean|)
// M = (f+eps)*e^{-0.5}  (theta=1)
//
// Validated identities (rel_err ~1.5e-7):
//   sd = S2 - S1*mean ; contrast = (8/9)*(1 - 2*eps*rsqrt(sd/8)) w/ bit-trick rsqrt
//
// This round: R3's layout (separate sp/sl float arrays, 1 px/thread,
// lane-contiguous LDS.32) but ALL 36 window loads batched upfront into
// registers (MLP ~36), then 4 pure-ALU feature blocks with tree-structured
// |dev| sums. Latency-structure fix, not instruction-count fix.

#define EPSF 1e-6f
#define EXPN 0.60653065971263342f      /* e^-0.5 */
#define EPSC (EPSF * EXPN)
#define KE   (EXPN / 9.0f)
#define KC   (8.0f / 9.0f * EXPN)
#define SROW 34

__global__ __launch_bounds__(256, 4)
void glcm_martingale_kernel(const float* __restrict__ x, float* __restrict__ out)
{
    __shared__ float sp[SROW * SROW];   // raw values, zero-padded halo
    __shared__ float sl[SROW * SROW];   // p * log(p + eps)

    const int bc    = blockIdx.z;
    const int tileX = blockIdx.x * 32;
    const int tileY = blockIdx.y * 32;
    const float* __restrict__ xin = x + (size_t)bc * 65536;

    const int tx  = threadIdx.x;        // 0..31
    const int ty  = threadIdx.y;        // 0..7
    const int tid = ty * 32 + tx;

    // ---- load 34x34 halo tile; plog computed once per element (R3-proven) ----
    #pragma unroll
    for (int i = tid; i < SROW * SROW; i += 256) {
        int r  = i / SROW;
        int cc = i - r * SROW;
        int gh = tileY - 1 + r;
        int gw = tileX - 1 + cc;
        float v = 0.0f;
        if ((unsigned)gh < 256u && (unsigned)gw < 256u)
            v = xin[gh * 256 + gw];
        sp[i] = v;
        sl[i] = v * __logf(v + EPSF);
    }
    __syncthreads();

    const int r0 = ty * 4;              // first output row in tile (rows r0..r0+5 used)

    const size_t plane = 65536;
    float* obase = out + (size_t)bc * 4 * plane
                       + (size_t)(tileY + r0) * 256 + (tileX + tx);

    // ---- batch-load all 6 smem rows into registers (36 LDS, high MLP) ----
    float pA[6], pB[6], pC[6];          // taps per row
    float rs[6], rq[6], rl[6];          // per-row sums of p, p^2, plog
    #pragma unroll
    for (int j = 0; j < 6; j++) {
        const float* rowp = sp + (r0 + j) * SROW + tx;
        float a = rowp[0], b = rowp[1], c = rowp[2];
        const float* rowl = sl + (r0 + j) * SROW + tx;
        float la = rowl[0], lb = rowl[1], lc = rowl[2];
        pA[j] = a; pB[j] = b; pC[j] = c;
        rs[j] = a + b + c;
        rq[j] = fmaf(a, a, fmaf(b, b, c * c));
        rl[j] = la + lb + lc;
    }

    // ---- 4 pure-ALU feature blocks ----
    #pragma unroll
    for (int k = 0; k < 4; k++) {
        float S1 = rs[k] + rs[k + 1] + rs[k + 2];
        float S2 = rq[k] + rq[k + 1] + rq[k + 2];
        float SL = rl[k] + rl[k + 1] + rl[k + 2];

        const float inv9 = 1.0f / 9.0f;
        float mean = S1 * inv9;
        float sd = fmaxf(fmaf(-S1, mean, S2), 1e-12f);   // sum (p-mean)^2

        // contrast = (8/9)*(1 - 2*eps*rsqrt(sd/8)); bit-trick rsqrt (no MUFU)
        float r  = __int_as_float(0x5f3759df - (__float_as_int(sd * 0.125f) >> 1));
        float cf = fmaxf(fmaf(-2.0f * EPSF, r, 1.0f), 0.0f);

        // homogeneity: tree-structured sum |p - mean| (short critical path)
        float d0 = fabsf(pA[k]     - mean);
        float d1 = fabsf(pB[k]     - mean);
        float d2 = fabsf(pC[k]     - mean);
        float d3 = fabsf(pA[k + 1] - mean);
        float d4 = fabsf(pB[k + 1] - mean);
        float d5 = fabsf(pC[k + 1] - mean);
        float d6 = fabsf(pA[k + 2] - mean);
        float d7 = fabsf(pB[k + 2] - mean);
        float d8 = fabsf(pC[k + 2] - mean);
        float s01 = d0 + d1, s23 = d2 + d3, s45 = d4 + d5, s67 = d6 + d7;
        float a = ((s01 + s23) + (s45 + s67)) + d8;
        float h = __fdividef(1.0f, fmaf(a, inv9, 1.0f));

        float* o = obase + (size_t)k * 256;
        o[0]         = fmaf(cf, KC,   EPSC);   // contrast
        o[plane]     = fmaf(S2, KE,   EPSC);   // energy
        o[2 * plane] = fmaf(SL, -KE,  EPSC);   // entropy
        o[3 * plane] = fmaf(h,  EXPN, EPSC);   // homogeneity
    }
}

extern "C" void kernel_launch(void* const* d_in, const int* in_sizes, int n_in,
                              void* d_out, int out_size)
{
    const float* x = (const float*)d_in[0];
    float* out     = (float*)d_out;

    dim3 block(32, 8, 1);                 // 256 threads, 1 px/thread, 4 rows each
    dim3 grid(256 / 32, 256 / 32, 128);   // 8 x 8 x 128 = 8192 blocks
    glcm_martingale_kernel<<<grid, block>>>(x, out);
}